// round 17
// baseline (speedup 1.0000x reference)
#include <cuda_runtime.h>
#include <cuda_fp16.h>
#include <stdint.h>
#include <math.h>

#define BB    2048
#define REPRK 8192
#define SS    24
#define DD    8
#define SBH   384   // S*BINS

// ===================== PTX helpers (non-arch-specific) ======================
__device__ __forceinline__ uint32_t smem_u32(const void* p) {
    uint32_t a;
    asm("{ .reg .u64 t; cvta.to.shared.u64 t, %1; cvt.u32.u64 %0, t; }" : "=r"(a) : "l"(p));
    return a;
}
__device__ __forceinline__ void cp16(uint32_t saddr, const void* g) {
    asm volatile("cp.async.cg.shared.global [%0], [%1], 16;" :: "r"(saddr), "l"(g));
}
#define CPCOMMIT asm volatile("cp.async.commit_group;" ::: "memory")
#define CPWAIT2  asm volatile("cp.async.wait_group 2;" ::: "memory")

__device__ __forceinline__ void ldsm4(uint32_t* r, uint32_t addr) {
    asm volatile("ldmatrix.sync.aligned.m8n8.x4.shared.b16 {%0,%1,%2,%3}, [%4];"
        : "=r"(r[0]), "=r"(r[1]), "=r"(r[2]), "=r"(r[3]) : "r"(addr));
}
__device__ __forceinline__ void sts16(uint32_t addr, uint4 v) {
    asm volatile("st.shared.v4.b32 [%0], {%1,%2,%3,%4};"
        :: "r"(addr), "r"(v.x), "r"(v.y), "r"(v.z), "r"(v.w));
}
__device__ __forceinline__ void mma_f32acc(float* d, const uint32_t* a, uint32_t b0, uint32_t b1) {
    asm volatile("mma.sync.aligned.m16n8k16.row.col.f32.f16.f16.f32 "
        "{%0,%1,%2,%3}, {%4,%5,%6,%7}, {%8,%9}, {%0,%1,%2,%3};"
        : "+f"(d[0]), "+f"(d[1]), "+f"(d[2]), "+f"(d[3])
        : "r"(a[0]), "r"(a[1]), "r"(a[2]), "r"(a[3]), "r"(b0), "r"(b1));
}
// 8 f32 -> 8 fp16 packed into uint4
__device__ __forceinline__ void ldg_cvt8(const float* __restrict__ p, uint4& out) {
    float4 v0 = *(const float4*)p;
    float4 v1 = *(const float4*)(p + 4);
    __half2 h0 = __floats2half2_rn(v0.x, v0.y);
    __half2 h1 = __floats2half2_rn(v0.z, v0.w);
    __half2 h2 = __floats2half2_rn(v1.x, v1.y);
    __half2 h3 = __floats2half2_rn(v1.z, v1.w);
    out.x = *(uint32_t*)&h0; out.y = *(uint32_t*)&h1;
    out.z = *(uint32_t*)&h2; out.w = *(uint32_t*)&h3;
}

// ===================== scratch (device globals) =============================
__device__ __half g_WrgbTh[(size_t)512 * REPRK];   // 8 MB
__device__ float g_rgb_part[2 * BB * 512];         // 8 MB: rgb splitk2, then t0/qb
__device__ __half g_xvh[BB * 512];
__device__ __half g_xqh[BB * 512];
__device__ __half g_vW1Th[512 * 512];
__device__ __half g_vW2Th[512 * 512];
__device__ __half g_qW1Th[512 * 512];
__device__ __half g_qW2Th[512 * 512];
__device__ __half g_t1h[BB * 512];
__device__ __half g_q1h[(size_t)BB * SS * 512];    // 50 MB (s-major rows)
__device__ __half g_q2pre[(size_t)BB * SS * 512];  // 50 MB (s-major rows, fp16)

// ===================== small helpers ========================================
__device__ __forceinline__ float silu(float z) { return z / (1.f + expf(-z)); }

// ===================== HMMA single-pass fp16 GEMM core (128x128 tile) =======
// 256 threads, 8 warps in 4x2 grid of 32x64 warp tiles. 4-stage ring.
template<bool HOUT>
__device__ __forceinline__ void gemm_core(
    const __half* __restrict__ A, const __half* __restrict__ B,
    void* __restrict__ Cv, int m0, int n0, int kbase, int lda, int N, int nch,
    char* smdyn) {
    const int tid = threadIdx.x;
    const int lane = tid & 31, wid = tid >> 5;
    const int wm = wid & 3, wn = wid >> 2;

    const int lrow = tid >> 2, lc = tid & 3;
    const int lpc = lc ^ ((lrow >> 1) & 3);
    const uint32_t sb0 = smem_u32(smdyn);
    const uint32_t s_store = sb0 + lrow * 64 + lpc * 16;
    const __half* gA = A + (size_t)(m0 + lrow) * lda + kbase + lc * 8;
    const __half* gB = B + (size_t)(n0 + lrow) * lda + kbase + lc * 8;
    const size_t l64 = (size_t)64 * lda;

#define LOADST(s, i) do { \
    uint32_t _so = s_store + (uint32_t)(s) * 16384u; \
    size_t _ko = (size_t)(i) * 32; \
    cp16(_so,               gA + _ko); \
    cp16(_so + 4096,        gA + l64 + _ko); \
    cp16(_so + 8192,        gB + _ko); \
    cp16(_so + 8192 + 4096, gB + l64 + _ko); } while (0)

    LOADST(0, 0); CPCOMMIT;
    LOADST(1, 1); CPCOMMIT;
    LOADST(2, 2); CPCOMMIT;

    float acc[2][8][4];
    #pragma unroll
    for (int mf = 0; mf < 2; mf++)
        #pragma unroll
        for (int nf = 0; nf < 8; nf++)
            #pragma unroll
            for (int r = 0; r < 4; r++) acc[mf][nf][r] = 0.f;

    const int r15 = lane & 15, ksel = lane >> 4;

    for (int i = 0; i < nch; i++) {
        CPWAIT2;
        __syncthreads();
        uint32_t sb = sb0 + (uint32_t)(i & 3) * 16384u;
        #pragma unroll
        for (int kt = 0; kt < 2; kt++) {
            const int cA = 2 * kt + ksel;
            uint32_t a[2][4], b[4][4];
            #pragma unroll
            for (int mf = 0; mf < 2; mf++) {
                int row = wm * 32 + mf * 16 + r15;
                uint32_t off = (uint32_t)(row * 64 + ((cA ^ ((row >> 1) & 3)) * 16));
                ldsm4(a[mf], sb + off);
            }
            #pragma unroll
            for (int nf4 = 0; nf4 < 4; nf4++) {
                int row = wn * 64 + nf4 * 16 + r15;
                uint32_t off = (uint32_t)(row * 64 + ((cA ^ ((row >> 1) & 3)) * 16));
                ldsm4(b[nf4], sb + 8192 + off);
            }
            #pragma unroll
            for (int mf = 0; mf < 2; mf++)
                #pragma unroll
                for (int nf4 = 0; nf4 < 4; nf4++) {
                    mma_f32acc(acc[mf][nf4 * 2],     a[mf], b[nf4][0], b[nf4][2]);
                    mma_f32acc(acc[mf][nf4 * 2 + 1], a[mf], b[nf4][1], b[nf4][3]);
                }
        }
        if (i + 3 < nch) LOADST((i + 3) & 3, i + 3);
        CPCOMMIT;
    }
#undef LOADST

    #pragma unroll
    for (int mf = 0; mf < 2; mf++)
        #pragma unroll
        for (int nf = 0; nf < 8; nf++) {
            int m = m0 + wm * 32 + mf * 16 + (lane >> 2);
            int n = n0 + wn * 64 + nf * 8 + (lane & 3) * 2;
            if (HOUT) {
                __half* Ch = (__half*)Cv;
                *(__half2*)&Ch[(size_t)m * N + n] = __floats2half2_rn(acc[mf][nf][0], acc[mf][nf][1]);
                *(__half2*)&Ch[(size_t)(m + 8) * N + n] = __floats2half2_rn(acc[mf][nf][2], acc[mf][nf][3]);
            } else {
                float* Cf = (float*)Cv;
                *(float2*)&Cf[(size_t)m * N + n] = make_float2(acc[mf][nf][0], acc[mf][nf][1]);
                *(float2*)&Cf[(size_t)(m + 8) * N + n] = make_float2(acc[mf][nf][2], acc[mf][nf][3]);
            }
        }
}

// rgb GEMM with fused f32->fp16 A conversion (A read directly from rgb_obs).
// grid (4, 16, 2) splitk2 over K=8192.
__global__ __launch_bounds__(256, 2)
void gemm_rgb(const float* __restrict__ A32, const __half* __restrict__ B,
              float* __restrict__ C) {
    extern __shared__ char smdyn[];
    const int tid = threadIdx.x;
    const int lane = tid & 31, wid = tid >> 5;
    const int wm = wid & 3, wn = wid >> 2;
    const int m0 = blockIdx.y * 128, n0 = blockIdx.x * 128;
    const int kbase = blockIdx.z * 4096;
    float* Cz = C + (size_t)blockIdx.z * BB * 512;
    const int nch = 128;

    const int lrow = tid >> 2, lc = tid & 3;
    const int lpc = lc ^ ((lrow >> 1) & 3);
    const uint32_t sb0 = smem_u32(smdyn);
    const uint32_t s_store = sb0 + lrow * 64 + lpc * 16;
    const float* gA0 = A32 + (size_t)(m0 + lrow) * REPRK + kbase + lc * 8;
    const float* gA1 = gA0 + (size_t)64 * REPRK;
    const __half* gB = B + (size_t)(n0 + lrow) * REPRK + kbase + lc * 8;
    const size_t l64 = (size_t)64 * REPRK;

    // prologue: stages 0..2
    #pragma unroll
    for (int s = 0; s < 3; s++) {
        uint4 a0, a1;
        ldg_cvt8(gA0 + (size_t)s * 32, a0);
        ldg_cvt8(gA1 + (size_t)s * 32, a1);
        uint32_t so = s_store + (uint32_t)s * 16384u;
        sts16(so, a0); sts16(so + 4096, a1);
        cp16(so + 8192,        gB + (size_t)s * 32);
        cp16(so + 8192 + 4096, gB + l64 + (size_t)s * 32);
        CPCOMMIT;
    }

    float acc[2][8][4];
    #pragma unroll
    for (int mf = 0; mf < 2; mf++)
        #pragma unroll
        for (int nf = 0; nf < 8; nf++)
            #pragma unroll
            for (int r = 0; r < 4; r++) acc[mf][nf][r] = 0.f;

    const int r15 = lane & 15, ksel = lane >> 4;

    for (int i = 0; i < nch; i++) {
        CPWAIT2;
        __syncthreads();
        // issue A loads for chunk i+3 (covered by this chunk's compute)
        uint4 pa0, pa1;
        const bool pre = (i + 3 < nch);
        if (pre) {
            ldg_cvt8(gA0 + (size_t)(i + 3) * 32, pa0);
            ldg_cvt8(gA1 + (size_t)(i + 3) * 32, pa1);
        }
        uint32_t sb = sb0 + (uint32_t)(i & 3) * 16384u;
        #pragma unroll
        for (int kt = 0; kt < 2; kt++) {
            const int cA = 2 * kt + ksel;
            uint32_t a[2][4], b[4][4];
            #pragma unroll
            for (int mf = 0; mf < 2; mf++) {
                int row = wm * 32 + mf * 16 + r15;
                uint32_t off = (uint32_t)(row * 64 + ((cA ^ ((row >> 1) & 3)) * 16));
                ldsm4(a[mf], sb + off);
            }
            #pragma unroll
            for (int nf4 = 0; nf4 < 4; nf4++) {
                int row = wn * 64 + nf4 * 16 + r15;
                uint32_t off = (uint32_t)(row * 64 + ((cA ^ ((row >> 1) & 3)) * 16));
                ldsm4(b[nf4], sb + 8192 + off);
            }
            #pragma unroll
            for (int mf = 0; mf < 2; mf++)
                #pragma unroll
                for (int nf4 = 0; nf4 < 4; nf4++) {
                    mma_f32acc(acc[mf][nf4 * 2],     a[mf], b[nf4][0], b[nf4][2]);
                    mma_f32acc(acc[mf][nf4 * 2 + 1], a[mf], b[nf4][1], b[nf4][3]);
                }
        }
        if (pre) {
            uint32_t so = s_store + (uint32_t)((i + 3) & 3) * 16384u;
            sts16(so, pa0); sts16(so + 4096, pa1);
            cp16(so + 8192,        gB + (size_t)(i + 3) * 32);
            cp16(so + 8192 + 4096, gB + l64 + (size_t)(i + 3) * 32);
        }
        CPCOMMIT;
    }

    #pragma unroll
    for (int mf = 0; mf < 2; mf++)
        #pragma unroll
        for (int nf = 0; nf < 8; nf++) {
            int m = m0 + wm * 32 + mf * 16 + (lane >> 2);
            int n = n0 + wn * 64 + nf * 8 + (lane & 3) * 2;
            *(float2*)&Cz[(size_t)m * 512 + n] = make_float2(acc[mf][nf][0], acc[mf][nf][1]);
            *(float2*)&Cz[(size_t)(m + 8) * 512 + n] = make_float2(acc[mf][nf][2], acc[mf][nf][3]);
        }
}

// vW1 + qW1 packed, full K each. grid (4, 16, 2): z = job
__global__ __launch_bounds__(256, 2)
void gemm_dualA(const __half* __restrict__ xvh, const __half* __restrict__ vB,
                const __half* __restrict__ xqh, const __half* __restrict__ qB,
                float* __restrict__ t0, float* __restrict__ qb) {
    extern __shared__ char smdyn[];
    int job = blockIdx.z;
    const __half* A = job ? xqh : xvh;
    const __half* B = job ? qB : vB;
    float* C = job ? qb : t0;
    gemm_core<false>(A, B, C, blockIdx.y * 128, blockIdx.x * 128, 0, 512, 512, 16, smdyn);
}

// qW2 (full, fp16 out) + vW2 (full K, f32 out). grid (4, 400)
__global__ __launch_bounds__(256, 2)
void gemm_dualB(const __half* __restrict__ q1h, const __half* __restrict__ qB,
                const __half* __restrict__ t1h, const __half* __restrict__ vB,
                __half* __restrict__ q2pre, float* __restrict__ t0) {
    extern __shared__ char smdyn[];
    int y = blockIdx.y;
    if (y < 384) {
        gemm_core<true>(q1h, qB, q2pre, y * 128, blockIdx.x * 128, 0, 512, 512, 16, smdyn);
    } else {
        gemm_core<false>(t1h, vB, t0, (y - 384) * 128, blockIdx.x * 128, 0, 512, 512, 16, smdyn);
    }
}

// ===================== merged prep (transposes only) ========================
// blocks [0,4096): trans_rgb; [4096,5120): trans4
#define NB_TRGB 4096
__global__ __launch_bounds__(256)
void prep_all(const float* __restrict__ vWr, const float* __restrict__ qWr, __half* __restrict__ Trgb,
              const float* __restrict__ W0, __half* __restrict__ T0,
              const float* __restrict__ W1, __half* __restrict__ T1,
              const float* __restrict__ W2, __half* __restrict__ T2,
              const float* __restrict__ W3, __half* __restrict__ T3) {
    __shared__ float t[32][33];
    int bidx = blockIdx.x;
    int tid = threadIdx.x;
    int tx = tid & 31, ty = tid >> 5;
    if (bidx < NB_TRGB) {
        int bx = bidx & 255, by = bidx >> 8;
        int k0 = bx * 32, n0 = by * 32;
        const float* src = (n0 < 256) ? vWr : qWr;
        int nb = (n0 < 256) ? n0 : (n0 - 256);
        #pragma unroll
        for (int i = 0; i < 4; i++)
            t[ty + i * 8][tx] = src[(size_t)(k0 + ty + i * 8) * 256 + nb + tx];
        __syncthreads();
        #pragma unroll
        for (int i = 0; i < 4; i++)
            Trgb[(size_t)(n0 + ty + i * 8) * REPRK + k0 + tx] = __float2half_rn(t[tx][ty + i * 8]);
        return;
    }
    int lb = bidx - NB_TRGB;
    int bx = lb & 15, by = (lb >> 4) & 15, z = lb >> 8;
    const float* W = z == 0 ? W0 : z == 1 ? W1 : z == 2 ? W2 : W3;
    __half* T = z == 0 ? T0 : z == 1 ? T1 : z == 2 ? T2 : T3;
    int k0 = bx * 32, n0 = by * 32;
    #pragma unroll
    for (int i = 0; i < 4; i++)
        t[ty + i * 8][tx] = W[(size_t)(k0 + ty + i * 8) * 512 + n0 + tx];
    __syncthreads();
    #pragma unroll
    for (int i = 0; i < 4; i++)
        T[(size_t)(n0 + ty + i * 8) * 512 + k0 + tx] = __float2half_rn(t[tx][ty + i * 8]);
}

// ===================== merged features (ln_tanh_rgb + low), warp-per-row ====
#define NB_LNT 171
__global__ __launch_bounds__(768)
void feat_k(const float* __restrict__ part,
            const float* __restrict__ vg, const float* __restrict__ vb,
            const float* __restrict__ qg, const float* __restrict__ qb,
            const float* __restrict__ low,
            const float* __restrict__ vWl, const float* __restrict__ vgl, const float* __restrict__ vbl,
            const float* __restrict__ qWl, const float* __restrict__ qgl, const float* __restrict__ qbl,
            __half* __restrict__ xvh, __half* __restrict__ xqh) {
    const int lane = threadIdx.x & 31, w = threadIdx.x >> 5;
    const size_t np = (size_t)BB * 512;
    if (blockIdx.x < NB_LNT) {
        int gw = blockIdx.x * 24 + w;
        if (gw >= 4096) return;
        int b = gw >> 1, hsel = gw & 1;
        float x[8], s1 = 0.f, s2 = 0.f;
        #pragma unroll
        for (int i = 0; i < 8; i++) {
            size_t off = (size_t)b * 512 + hsel * 256 + lane + i * 32;
            x[i] = part[off] + part[off + np];
            s1 += x[i]; s2 += x[i] * x[i];
        }
        #pragma unroll
        for (int o = 16; o > 0; o >>= 1) {
            s1 += __shfl_xor_sync(0xffffffffu, s1, o);
            s2 += __shfl_xor_sync(0xffffffffu, s2, o);
        }
        float mu = s1 * (1.f / 256.f);
        float inv = rsqrtf(s2 * (1.f / 256.f) - mu * mu + 1e-5f);
        const float* g  = hsel ? qg : vg;
        const float* be = hsel ? qb : vb;
        __half* dst = hsel ? xqh : xvh;
        #pragma unroll
        for (int i = 0; i < 8; i++) {
            int col = lane + i * 32;
            dst[(size_t)b * 512 + col] = __float2half_rn(tanhf((x[i] - mu) * inv * g[col] + be[col]));
        }
    } else {
        int gw = (blockIdx.x - NB_LNT) * 24 + w;
        if (gw >= 4096) return;
        int b = gw >> 1, path = gw & 1;
        const float* W  = path ? qWl : vWl;
        const float* g  = path ? qgl : vgl;
        const float* be = path ? qbl : vbl;
        __half* dst = path ? xqh : xvh;
        float myv = low[b * 32 + lane];
        float sv[8];
        #pragma unroll
        for (int i = 0; i < 8; i++) sv[i] = 0.f;
        #pragma unroll
        for (int k = 0; k < 32; k++) {
            float lk = __shfl_sync(0xffffffffu, myv, k);
            #pragma unroll
            for (int i = 0; i < 8; i++)
                sv[i] += lk * W[k * 256 + lane + i * 32];
        }
        float s1 = 0.f, s2 = 0.f;
        #pragma unroll
        for (int i = 0; i < 8; i++) { s1 += sv[i]; s2 += sv[i] * sv[i]; }
        #pragma unroll
        for (int o = 16; o > 0; o >>= 1) {
            s1 += __shfl_xor_sync(0xffffffffu, s1, o);
            s2 += __shfl_xor_sync(0xffffffffu, s2, o);
        }
        float mu = s1 * (1.f / 256.f);
        float inv = rsqrtf(s2 * (1.f / 256.f) - mu * mu + 1e-5f);
        #pragma unroll
        for (int i = 0; i < 8; i++) {
            int col = lane + i * 32;
            dst[(size_t)b * 512 + 256 + col] =
                __float2half_rn(tanhf((sv[i] - mu) * inv * g[col] + be[col]));
        }
    }
}

// ===================== mid_k: warp-per-slot =================================
__global__ __launch_bounds__(768)
void mid_k(const float* __restrict__ qb, const int* __restrict__ cat,
           const float* __restrict__ qW1, const float* __restrict__ qg1, const float* __restrict__ qb1,
           const float* __restrict__ t0, const float* __restrict__ vg1, const float* __restrict__ vb1,
           __half* __restrict__ q1h, __half* __restrict__ t1h) {
    const int lane = threadIdx.x & 31, w = threadIdx.x >> 5;
    if (blockIdx.x < BB) {
        __shared__ float wact[8 * 512];
        int b = blockIdx.x;
        for (int i = threadIdx.x; i < 8 * 512; i += 768)
            wact[i] = qW1[(size_t)(512 + (i >> 9)) * 512 + (i & 511)];
        int s = w;
        float myas = 0.f;
        if (lane < 8) {
            int ls = s >> 3, ds = s & 7;
            int lvl = ls + (lane < ds ? 1 : 0);
            float lowv = -1.f, width = 2.f, mid = 0.f;
            for (int l = 0; l < lvl; l++) {
                float wd = width * (1.f / 16.f);
                float c = (float)cat[(b * 3 + l) * 8 + lane];
                float nl = lowv + c * wd;
                mid = nl + 0.5f * wd;
                lowv = nl; width = wd;
            }
            myas = (lvl == 0) ? 0.f : mid;
        }
        float x[16];
        #pragma unroll
        for (int i = 0; i < 16; i++)
            x[i] = qb[(size_t)b * 512 + lane + i * 32];
        __syncthreads();
        #pragma unroll
        for (int d = 0; d < 8; d++) {
            float av = __shfl_sync(0xffffffffu, myas, d);
            #pragma unroll
            for (int i = 0; i < 16; i++)
                x[i] += av * wact[d * 512 + lane + i * 32];
        }
        float s1 = 0.f, s2 = 0.f;
        #pragma unroll
        for (int i = 0; i < 16; i++) { s1 += x[i]; s2 += x[i] * x[i]; }
        #pragma unroll
        for (int o = 16; o > 0; o >>= 1) {
            s1 += __shfl_xor_sync(0xffffffffu, s1, o);
            s2 += __shfl_xor_sync(0xffffffffu, s2, o);
        }
        float mu = s1 * (1.f / 512.f);
        float inv = rsqrtf(s2 * (1.f / 512.f) - mu * mu + 1e-5f);
        size_t row = (size_t)s * BB + b;
        #pragma unroll
        for (int i = 0; i < 16; i++) {
            int col = lane + i * 32;
            q1h[row * 512 + col] =
                __float2half_rn(silu((x[i] - mu) * inv * qg1[col] + qb1[col]));
        }
    } else {
        int gw = (blockIdx.x - BB) * 24 + w;
        if (gw >= BB) return;
        size_t rowo = (size_t)gw * 512;
        float x[16], s1 = 0.f, s2 = 0.f;
        #pragma unroll
        for (int i = 0; i < 16; i++) {
            x[i] = t0[rowo + lane + i * 32];
            s1 += x[i]; s2 += x[i] * x[i];
        }
        #pragma unroll
        for (int o = 16; o > 0; o >>= 1) {
            s1 += __shfl_xor_sync(0xffffffffu, s1, o);
            s2 += __shfl_xor_sync(0xffffffffu, s2, o);
        }
        float mu = s1 * (1.f / 512.f);
        float inv = rsqrtf(s2 * (1.f / 512.f) - mu * mu + 1e-5f);
        #pragma unroll
        for (int i = 0; i < 16; i++) {
            int col = lane + i * 32;
            t1h[rowo + col] =
                __float2half_rn(silu((x[i] - mu) * inv * vg1[col] + vb1[col]));
        }
    }
}

// ---- fused LN + SiLU + HMMA diagonal q-head, plus value head (merged) -----
#define LNW 520
__global__ __launch_bounds__(256)
void lnhead_q(const __half* __restrict__ pre, const float* __restrict__ g,
              const float* __restrict__ be, const float* __restrict__ Wh,
              const float* __restrict__ bh, float* __restrict__ out,
              const float* __restrict__ t0, const float* __restrict__ vg2,
              const float* __restrict__ vb2, const float* __restrict__ vWh,
              const float* __restrict__ vbh, float* __restrict__ outv) {
    const int tid = threadIdx.x, lane = tid & 31, w = tid >> 5;
    if (blockIdx.x >= 768) {
        int b = (blockIdx.x - 768) * 8 + w;
        float x[16], s1 = 0.f, s2 = 0.f;
        #pragma unroll
        for (int i = 0; i < 16; i++) {
            x[i] = t0[(size_t)b * 512 + lane + i * 32];
            s1 += x[i]; s2 += x[i] * x[i];
        }
        #pragma unroll
        for (int o = 16; o > 0; o >>= 1) {
            s1 += __shfl_xor_sync(0xffffffffu, s1, o);
            s2 += __shfl_xor_sync(0xffffffffu, s2, o);
        }
        float mu = s1 * (1.f / 512.f);
        float inv = rsqrtf(s2 * (1.f / 512.f) - mu * mu + 1e-5f);
        float acc = 0.f;
        #pragma unroll
        for (int i = 0; i < 16; i++) {
            int col = lane + i * 32;
            acc += silu((x[i] - mu) * inv * vg2[col] + vb2[col]) * vWh[col];
        }
        #pragma unroll
        for (int o = 16; o > 0; o >>= 1)
            acc += __shfl_xor_sync(0xffffffffu, acc, o);
        if (lane == 0) outv[b] = acc + vbh[0];
        return;
    }
    extern __shared__ __half smh[];
    __half* whsT = smh;              // [16][LNW]
    __half* ys   = smh + 16 * LNW;   // [64][LNW]
    const int r0 = blockIdx.x * 64;
    const int s16 = (r0 >> 11) * 16;

    for (int i = tid; i < 16 * 512; i += 256) {
        int n = i & 15, k = i >> 4;
        whsT[n * LNW + k] = __float2half_rn(Wh[(size_t)k * SBH + s16 + n]);
    }

    for (int rr = w; rr < 64; rr += 8) {
        const __half2* row = (const __half2*)(pre + (size_t)(r0 + rr) * 512);
        float2 v[8];
        float s1 = 0.f, s2 = 0.f;
        #pragma unroll
        for (int i = 0; i < 8; i++) {
            v[i] = __half22float2(row[lane + i * 32]);
            s1 += v[i].x + v[i].y;
            s2 += v[i].x * v[i].x + v[i].y * v[i].y;
        }
        #pragma unroll
        for (int o = 16; o > 0; o >>= 1) {
            s1 += __shfl_xor_sync(0xffffffffu, s1, o);
            s2 += __shfl_xor_sync(0xffffffffu, s2, o);
        }
        float mu = s1 * (1.f / 512.f);
        float inv = rsqrtf(s2 * (1.f / 512.f) - mu * mu + 1e-5f);
        __half2* yr = (__half2*)(ys + rr * LNW);
        #pragma unroll
        for (int i = 0; i < 8; i++) {
            int col = 2 * (lane + i * 32);
            float2 gg = *(const float2*)&g[col];
            float2 bb = *(const float2*)&be[col];
            float y0 = silu((v[i].x - mu) * inv * gg.x + bb.x);
            float y1 = silu((v[i].y - mu) * inv * gg.y + bb.y);
            yr[lane + i * 32] = __floats2half2_rn(y0, y1);
        }
    }
    __syncthreads();

    if (w < 4) {
        const int mt = w;
        const int r15 = lane & 15, ks = lane >> 4;
        const uint32_t abase = smem_u32(ys)   + (uint32_t)((mt * 16 + r15) * (LNW * 2) + ks * 16);
        const uint32_t bbase = smem_u32(whsT) + (uint32_t)(r15 * (LNW * 2) + ks * 16);
        float acc[2][4] = {};
        #pragma unroll 4
        for (int kk = 0; kk < 32; kk++) {
            uint32_t a[4], b[4];
            ldsm4(a, abase + kk * 32);
            ldsm4(b, bbase + kk * 32);
            mma_f32acc(acc[0], a, b[0], b[2]);
            mma_f32acc(acc[1], a, b[1], b[3]);
        }
        int rloc = mt * 16 + (lane >> 2);
        int brow0 = (r0 + rloc) & (BB - 1);
        int brow1 = (r0 + rloc + 8) & (BB - 1);
        #pragma unroll
        for (int t = 0; t < 2; t++) {
            int col = t * 8 + (lane & 3) * 2;
            float2 bias = *(const float2*)&bh[s16 + col];
            *(float2*)&out[(size_t)brow0 * SBH + s16 + col] =
                make_float2(acc[t][0] + bias.x, acc[t][1] + bias.y);
            *(float2*)&out[(size_t)brow1 * SBH + s16 + col] =
                make_float2(acc[t][2] + bias.x, acc[t][3] + bias.y);
        }
    }
}

// ===================== launch ================================================
#define GEMM_DSMEM 65536
#define LNHEAD_DSMEM ((16 + 64) * LNW * 2)

extern "C" void kernel_launch(void* const* d_in, const int* in_sizes, int n_in,
                              void* d_out, int out_size) {
    const float* rgb_obs = (const float*)d_in[0];
    const float* low_obs = (const float*)d_in[1];
    const int*   category = (const int*)d_in[2];
    const float* v_W_rgb = (const float*)d_in[3];
    const float* v_g_rgb = (const float*)d_in[4];
    const float* v_b_rgb = (const float*)d_in[5];
    const float* v_W_low = (const float*)d_in[6];
    const float* v_g_low = (const float*)d_in[7];
    const float* v_b_low = (const float*)d_in[8];
    const float* v_W1 = (const float*)d_in[9];
    const float* v_g1 = (const float*)d_in[10];
    const float* v_b1 = (const float*)d_in[11];
    const float* v_W2 = (const float*)d_in[12];
    const float* v_g2 = (const float*)d_in[13];
    const float* v_b2 = (const float*)d_in[14];
    const float* v_Wh = (const float*)d_in[15];
    const float* v_bh = (const float*)d_in[16];
    const float* q_W_rgb = (const float*)d_in[17];
    const float* q_g_rgb = (const float*)d_in[18];
    const float* q_b_rgb = (const float*)d_in[19];
    const float* q_W_low = (const float*)d_in[20];
    const float* q_g_low = (const float*)d_in[21];
    const float* q_b_low = (const float*)d_in[22];
    const float* q_W1 = (const float*)d_in[23];
    const float* q_g1 = (const float*)d_in[24];
    const float* q_b1 = (const float*)d_in[25];
    const float* q_W2 = (const float*)d_in[26];
    const float* q_g2 = (const float*)d_in[27];
    const float* q_b2 = (const float*)d_in[28];
    const float* q_Wh = (const float*)d_in[29];
    const float* q_bh = (const float*)d_in[30];

    float* out_value = (float*)d_out;
    float* out_adv   = out_value + BB;

    cudaFuncSetAttribute(gemm_rgb,   cudaFuncAttributeMaxDynamicSharedMemorySize, GEMM_DSMEM);
    cudaFuncSetAttribute(gemm_dualA, cudaFuncAttributeMaxDynamicSharedMemorySize, GEMM_DSMEM);
    cudaFuncSetAttribute(gemm_dualB, cudaFuncAttributeMaxDynamicSharedMemorySize, GEMM_DSMEM);
    cudaFuncSetAttribute(lnhead_q,   cudaFuncAttributeMaxDynamicSharedMemorySize, LNHEAD_DSMEM);

    __half *WrgbT, *xvh, *xqh;
    __half *vW1T, *vW2T, *qW1T, *qW2T;
    __half *t1h, *q1h, *q2pre;
    float *rgb_part;
    cudaGetSymbolAddress((void**)&WrgbT, g_WrgbTh);
    cudaGetSymbolAddress((void**)&rgb_part, g_rgb_part);
    cudaGetSymbolAddress((void**)&xvh, g_xvh);
    cudaGetSymbolAddress((void**)&xqh, g_xqh);
    cudaGetSymbolAddress((void**)&vW1T, g_vW1Th);
    cudaGetSymbolAddress((void**)&vW2T, g_vW2Th);
    cudaGetSymbolAddress((void**)&qW1T, g_qW1Th);
    cudaGetSymbolAddress((void**)&qW2T, g_qW2Th);
    cudaGetSymbolAddress((void**)&t1h, g_t1h);
    cudaGetSymbolAddress((void**)&q1h, g_q1h);
    cudaGetSymbolAddress((void**)&q2pre, g_q2pre);

    float* t0 = rgb_part;                        // slice 0
    float* qb = rgb_part + (size_t)BB * 512;     // slice 1

    // ---- prep (weight transposes only; A conversion fused into gemm_rgb) ----
    prep_all<<<NB_TRGB + 1024, 256>>>(v_W_rgb, q_W_rgb, WrgbT,
                                      v_W1, vW1T, v_W2, vW2T, q_W1, qW1T, q_W2, qW2T);

    // ---- shared rgb features (splitk2, reduce folded into feat) ----
    gemm_rgb<<<dim3(4, BB / 128, 2), 256, GEMM_DSMEM>>>(rgb_obs, WrgbT, rgb_part);
    feat_k<<<2 * NB_LNT, 768>>>(rgb_part, v_g_rgb, v_b_rgb, q_g_rgb, q_b_rgb,
                                low_obs, v_W_low, v_g_low, v_b_low,
                                q_W_low, q_g_low, q_b_low, xvh, xqh);

    // ---- layer 1 (v + q packed, full K) ----
    gemm_dualA<<<dim3(4, 16, 2), 256, GEMM_DSMEM>>>(xvh, vW1T, xqh, qW1T, t0, qb);
    mid_k<<<BB + (BB + 23) / 24, 768>>>(qb, category, q_W1, q_g1, q_b1,
                                        t0, v_g1, v_b1, q1h, t1h);

    // ---- layer 2 ----
    gemm_dualB<<<dim3(4, 400), 256, GEMM_DSMEM>>>(q1h, qW2T, t1h, vW2T, q2pre, t0);

    // ---- heads (q head + value head in one launch) ----
    lnhead_q<<<1024, 256, LNHEAD_DSMEM>>>(q2pre, q_g2, q_b2, q_Wh, q_bh, out_adv,
                                          t0, v_g2, v_b2, v_Wh, v_bh, out_value);
}